// round 15
// baseline (speedup 1.0000x reference)
#include <cuda_runtime.h>
#include <cuda_fp16.h>
#include <cstdint>
#include <cstddef>

#define HN     16
#define DMODEL 1024
#define NSEQ   2048
#define NB     2
#define HD     64
#define LN_EPS 1e-5f
#define SSTR   40          // smem stride (halfs) for k=32 tiles
#define FSTR   72          // smem stride (halfs) aw/vsm/etile rows
#define ITILE  16
#define JCH    64

typedef unsigned long long u64;

// ---------------- scratch (device globals; no allocation allowed) ----------
__device__ __half g_qh [(size_t)NB * NSEQ * DMODEL];     // q fp16 (pre-scaled)
__device__ __half g_kh [(size_t)NB * NSEQ * 1024];       // k fp16
__device__ __half g_vh [(size_t)NB * NSEQ * 1024];       // v fp16 token-major
__device__ __half g_vth[(size_t)NB * DMODEL * NSEQ];     // v fp16 transposed
__device__ __half g_E [(size_t)NB * HN * NSEQ * NSEQ];   // exp(scores), fp16
__device__ float  g_rowsum[NB * HN * NSEQ];

// ---------------- fast exp on the FMA pipe (avoid MUFU.EX2) ----------------
__device__ __forceinline__ float fast_exp(float x) {
    float t = x * 1.4426950408889634f;
    float r = rintf(t);
    float f = t - r;
    float p =      1.5403530394e-4f;
    p = fmaf(p, f, 1.3333558146e-3f);
    p = fmaf(p, f, 9.6181291076e-3f);
    p = fmaf(p, f, 5.5504108665e-2f);
    p = fmaf(p, f, 2.4022650696e-1f);
    p = fmaf(p, f, 6.9314718056e-1f);
    p = fmaf(p, f, 1.0f);
    return p * __int_as_float(((int)r + 127) << 23);
}

// ------------------------- mma.sync / ldmatrix ------------------------------
__device__ __forceinline__ void mma16816(
    float (&c)[4], const uint32_t (&a)[4], uint32_t b0, uint32_t b1)
{
    asm volatile(
        "mma.sync.aligned.m16n8k16.row.col.f32.f16.f16.f32 "
        "{%0,%1,%2,%3}, {%4,%5,%6,%7}, {%8,%9}, {%0,%1,%2,%3};"
        : "+f"(c[0]), "+f"(c[1]), "+f"(c[2]), "+f"(c[3])
        : "r"(a[0]), "r"(a[1]), "r"(a[2]), "r"(a[3]), "r"(b0), "r"(b1));
}
__device__ __forceinline__ void ldsm_x4(uint32_t (&r)[4], uint32_t addr) {
    asm volatile("ldmatrix.sync.aligned.m8n8.x4.shared.b16 {%0,%1,%2,%3}, [%4];"
        : "=r"(r[0]), "=r"(r[1]), "=r"(r[2]), "=r"(r[3]) : "r"(addr));
}
__device__ __forceinline__ void ldsm_x4_t(uint32_t (&r)[4], uint32_t addr) {
    asm volatile("ldmatrix.sync.aligned.m8n8.x4.trans.shared.b16 {%0,%1,%2,%3}, [%4];"
        : "=r"(r[0]), "=r"(r[1]), "=r"(r[2]), "=r"(r[3]) : "r"(addr));
}

// Stage 128 x 32 fp32 tile as fp16, stride SSTR (gemm inputs).
__device__ __forceinline__ void stage_f32(
    uint16_t* __restrict__ dst, const float* __restrict__ src,
    size_t stride, int tid)
{
#pragma unroll
    for (int s = 0; s < 4; s++) {
        int idx = s * 256 + tid;
        int row = idx >> 3;
        int cg  = idx & 7;
        float4 v = *(const float4*)(src + (size_t)row * stride + cg * 4);
        __half2 h01 = __floats2half2_rn(v.x, v.y);
        __half2 h23 = __floats2half2_rn(v.z, v.w);
        *(uint2*)(dst + row * SSTR + cg * 4)
            = make_uint2(*(uint32_t*)&h01, *(uint32_t*)&h23);
    }
}
// Pure copy of a 128 x 32 fp16 tile into smem (scores staging; no cvt).
__device__ __forceinline__ void stage_copy(
    uint16_t* __restrict__ dst, const __half* __restrict__ src,
    size_t stride, int tid)
{
#pragma unroll
    for (int s = 0; s < 2; s++) {
        int idx = s * 256 + tid;
        int row = idx >> 2;
        int cq  = idx & 3;
        *(uint4*)(dst + row * SSTR + cq * 8)
            = *(const uint4*)(src + (size_t)row * stride + cq * 8);
    }
}

// ---- q/kv GEMM: C[128x128] = A @ B^T, fp32 in, fp16 out -------------------
__global__ void __launch_bounds__(256, 2) gemm_hmma_kernel(
    const float* __restrict__ A, const float* __restrict__ B,
    float alpha, __half* __restrict__ Ck, __half* __restrict__ Cv)
{
    __shared__ __align__(16) uint16_t sA[128 * SSTR];
    __shared__ __align__(16) uint16_t sB[128 * SSTR];
    const int tid  = threadIdx.x;
    const int wid  = tid >> 5;
    const int lane = tid & 31;
    const int wm = wid & 3, wn = wid >> 2;
    const int g = lane >> 2, t = lane & 3;
    const int m0 = blockIdx.y << 7, n0 = blockIdx.x << 7;
    const float* Ap = A + (size_t)m0 * DMODEL;
    const float* Bp = B + (size_t)n0 * DMODEL;

    const uint32_t aoff = (uint32_t)((lane & 15) * (SSTR * 2) + (lane >> 4) * 16);
    const uint32_t boff = (uint32_t)(((lane & 7) + ((lane >> 4) * 8)) * (SSTR * 2)
                                     + ((lane >> 3) & 1) * 16);
    const uint32_t aB = (uint32_t)__cvta_generic_to_shared(sA)
                        + aoff + (uint32_t)(wm * 32 * SSTR * 2);
    const uint32_t bB = (uint32_t)__cvta_generic_to_shared(sB)
                        + boff + (uint32_t)(wn * 64 * SSTR * 2);

    float acc[2][8][4];
#pragma unroll
    for (int mt = 0; mt < 2; mt++)
#pragma unroll
        for (int nt = 0; nt < 8; nt++)
#pragma unroll
            for (int q = 0; q < 4; q++) acc[mt][nt][q] = 0.f;

    for (int i = 0; i < DMODEL / 32; i++) {
        __syncthreads();
        stage_f32(sA, Ap + (size_t)i * 32, DMODEL, tid);
        stage_f32(sB, Bp + (size_t)i * 32, DMODEL, tid);
        __syncthreads();
#pragma unroll
        for (int ks = 0; ks < 2; ks++) {
            uint32_t ah[2][4];
            ldsm_x4(ah[0], aB + ks * 32);
            ldsm_x4(ah[1], aB + 16 * SSTR * 2 + ks * 32);
#pragma unroll
            for (int np = 0; np < 4; np++) {
                uint32_t bh[4];
                ldsm_x4(bh, bB + np * 16 * SSTR * 2 + ks * 32);
                mma16816(acc[0][2*np],   ah[0], bh[0], bh[1]);
                mma16816(acc[1][2*np],   ah[1], bh[0], bh[1]);
                mma16816(acc[0][2*np+1], ah[0], bh[2], bh[3]);
                mma16816(acc[1][2*np+1], ah[1], bh[2], bh[3]);
            }
        }
    }

    const bool isk = (Cv == nullptr) || (n0 < 1024);
    __half* Co = isk ? Ck : Cv;
    const int colbase = isk ? n0 : (n0 - 1024);
#pragma unroll
    for (int mt = 0; mt < 2; mt++) {
        int r0 = m0 + wm * 32 + mt * 16 + g;
#pragma unroll
        for (int nt = 0; nt < 8; nt++) {
            int col = colbase + wn * 64 + nt * 8 + 2 * t;
            __half2 p01 = __floats2half2_rn(acc[mt][nt][0] * alpha,
                                            acc[mt][nt][1] * alpha);
            __half2 p23 = __floats2half2_rn(acc[mt][nt][2] * alpha,
                                            acc[mt][nt][3] * alpha);
            *(uint32_t*)&Co[(size_t)r0 * 1024 + col]       = *(uint32_t*)&p01;
            *(uint32_t*)&Co[(size_t)(r0 + 8) * 1024 + col] = *(uint32_t*)&p23;
        }
    }
}

// ---- scores: E = exp(q k^T) per head, fp16 in/out + rowsum -----------------
__global__ void __launch_bounds__(256, 2) scores_hmma_kernel()
{
    __shared__ __align__(16) uint16_t sA[128 * SSTR];
    __shared__ __align__(16) uint16_t sB[128 * SSTR];
    const int tid  = threadIdx.x;
    const int wid  = tid >> 5;
    const int lane = tid & 31;
    const int wm = wid & 3, wn = wid >> 2;
    const int g = lane >> 2, t = lane & 3;
    const int bh = blockIdx.z, b = bh >> 4, h = bh & 15;
    const int i0 = blockIdx.y << 7, j0 = blockIdx.x << 7;

    const __half* Ap = g_qh + (size_t)(b * NSEQ + i0) * DMODEL + h * HD;
    const __half* Bp = g_kh + (size_t)(b * NSEQ + j0) * 1024 + h * HD;
    __half* Cb = g_E + (size_t)bh * NSEQ * NSEQ + (size_t)i0 * NSEQ + j0;
    float* rowsum = g_rowsum + bh * NSEQ + i0;

    const uint32_t aoff = (uint32_t)((lane & 15) * (SSTR * 2) + (lane >> 4) * 16);
    const uint32_t boff = (uint32_t)(((lane & 7) + ((lane >> 4) * 8)) * (SSTR * 2)
                                     + ((lane >> 3) & 1) * 16);
    const uint32_t aB = (uint32_t)__cvta_generic_to_shared(sA)
                        + aoff + (uint32_t)(wm * 32 * SSTR * 2);
    const uint32_t bB = (uint32_t)__cvta_generic_to_shared(sB)
                        + boff + (uint32_t)(wn * 64 * SSTR * 2);

    float acc[2][8][4];
#pragma unroll
    for (int mt = 0; mt < 2; mt++)
#pragma unroll
        for (int nt = 0; nt < 8; nt++)
#pragma unroll
            for (int q = 0; q < 4; q++) acc[mt][nt][q] = 0.f;

#pragma unroll
    for (int i = 0; i < HD / 32; i++) {
        __syncthreads();
        stage_copy(sA, Ap + i * 32, DMODEL, tid);
        stage_copy(sB, Bp + i * 32, 1024, tid);
        __syncthreads();
#pragma unroll
        for (int ks = 0; ks < 2; ks++) {
            uint32_t ah[2][4];
            ldsm_x4(ah[0], aB + ks * 32);
            ldsm_x4(ah[1], aB + 16 * SSTR * 2 + ks * 32);
#pragma unroll
            for (int np = 0; np < 4; np++) {
                uint32_t bh4[4];
                ldsm_x4(bh4, bB + np * 16 * SSTR * 2 + ks * 32);
                mma16816(acc[0][2*np],   ah[0], bh4[0], bh4[1]);
                mma16816(acc[1][2*np],   ah[1], bh4[0], bh4[1]);
                mma16816(acc[0][2*np+1], ah[0], bh4[2], bh4[3]);
                mma16816(acc[1][2*np+1], ah[1], bh4[2], bh4[3]);
            }
        }
    }

#pragma unroll
    for (int mt = 0; mt < 2; mt++) {
        int r0 = wm * 32 + mt * 16 + g;
        float rs0 = 0.f, rs1 = 0.f;
#pragma unroll
        for (int nt = 0; nt < 8; nt++) {
            int col = wn * 64 + nt * 8 + 2 * t;
            float e0 = fast_exp(acc[mt][nt][0]);
            float e1 = fast_exp(acc[mt][nt][1]);
            float e2 = fast_exp(acc[mt][nt][2]);
            float e3 = fast_exp(acc[mt][nt][3]);
            rs0 += e0 + e1;
            rs1 += e2 + e3;
            __half2 p01 = __floats2half2_rn(e0, e1);
            __half2 p23 = __floats2half2_rn(e2, e3);
            *(uint32_t*)&Cb[(size_t)r0 * NSEQ + col]       = *(uint32_t*)&p01;
            *(uint32_t*)&Cb[(size_t)(r0 + 8) * NSEQ + col] = *(uint32_t*)&p23;
        }
        rs0 += __shfl_down_sync(0xffffffffu, rs0, 1, 4);
        rs0 += __shfl_down_sync(0xffffffffu, rs0, 2, 4);
        rs1 += __shfl_down_sync(0xffffffffu, rs1, 1, 4);
        rs1 += __shfl_down_sync(0xffffffffu, rs1, 2, 4);
        if (t == 0) {
            atomicAdd(&rowsum[r0], rs0);
            atomicAdd(&rowsum[r0 + 8], rs1);
        }
    }
}

// --------- transpose v: [b][j][c] fp16 -> [b][c][j] fp16 --------------------
__global__ void __launch_bounds__(256) transpose_v_kernel()
{
    __shared__ __half t[32][33];
    int j0 = blockIdx.x << 5, c0 = blockIdx.y << 5, b = blockIdx.z;
    int tx = threadIdx.x, ty = threadIdx.y;
#pragma unroll
    for (int i = 0; i < 4; i++)
        t[ty + i * 8][tx] =
            g_vh[((size_t)(b * NSEQ) + j0 + ty + i * 8) * 1024 + c0 + tx];
    __syncthreads();
#pragma unroll
    for (int i = 0; i < 4; i++)
        g_vth[((size_t)b * DMODEL + c0 + ty + i * 8) * NSEQ + j0 + tx] =
            t[tx][ty + i * 8];
}

// ---- FUSED: MMA talk-mix + LayerNorm + (aw @ v) ----------------------------
// Block = (b, 16-row i-tile), 512 threads = 16 warps. Warp w: mix row w (all
// 16 heads via tensor-core W' @ E), then head w for PV. W' = W * rinv folded,
// split hi/lo fp16 (exact to 2^-22). aw stored with per-head XOR swizzle.
// (Validated verbatim in R11: passed, rel_err 6.0e-4.)
__global__ void __launch_bounds__(512, 1) fused_pv_kernel(
    float* __restrict__ out, const float* __restrict__ Wtalk,
    const float* __restrict__ gamma, const float* __restrict__ beta)
{
    extern __shared__ __align__(16) char sm[];
    __half* aw   = (__half*)sm;                        // 16*16*72*2 = 36864
    __half* vsm  = (__half*)(sm + 36864);              // 16*64*72*2 = 147456
    __half* et   = (__half*)(sm + 184320);             // 16*16*72*2 = 36864
    float*  rinv = (float*)(sm + 221184);              // [h][i] 256
    float*  gam  = rinv + 256;
    float*  bet  = gam + 16;

    const int tid  = threadIdx.x;
    const int wid  = tid >> 5;
    const int lane = tid & 31;
    const int b  = blockIdx.y;
    const int i0 = blockIdx.x * ITILE;
    const int g8 = lane >> 2, t = lane & 3;

    if (tid < 256) {
        int h = tid >> 4, i = tid & 15;
        rinv[h * 16 + i] = 1.0f / g_rowsum[(size_t)(b * HN + h) * NSEQ + i0 + i];
    }
    if (tid < 16) { gam[tid] = gamma[tid]; bet[tid] = beta[tid]; }
    __syncthreads();

    const uint32_t awS  = (uint32_t)__cvta_generic_to_shared(aw);
    const uint32_t vsmS = (uint32_t)__cvta_generic_to_shared(vsm);
    const uint32_t etS  = (uint32_t)__cvta_generic_to_shared(et);

    // ---- build W' = W * rinv[.,wid] hi/lo tiles (in vsm alias), ldsm once --
    uint32_t wh[4], wl[4];
    {
        __half* wtile = vsm + wid * 768;               // 16x24 hi, then lo
#pragma unroll
        for (int s = 0; s < 8; s++) {
            int idx = s * 32 + lane;
            int g = idx >> 4, h = idx & 15;
            float w = Wtalk[g * 16 + h] * rinv[h * 16 + wid];
            __half hi = __float2half_rn(w);
            __half lo = __float2half_rn(w - __half2float(hi));
            wtile[g * 24 + h]       = hi;
            wtile[384 + g * 24 + h] = lo;
        }
        __syncwarp();
        uint32_t wS = vsmS + wid * 1536
                    + (uint32_t)((lane & 15) * 48 + ((lane >> 4) << 4));
        ldsm_x4(wh, wS);
        ldsm_x4(wl, wS + 768);
    }
    __syncthreads();                                   // vsm reused below

    const uint32_t eB = etS + (uint32_t)(wid * 2304)
                      + (uint32_t)((lane & 15) * 144 + ((lane >> 4) << 4));
    const uint32_t bB = vsmS + (uint32_t)(wid * 64 * FSTR * 2)
                      + (uint32_t)(((lane & 7) + ((lane >> 4) * 8)) * (FSTR * 2)
                                   + ((lane >> 3) & 1) * 16);
    const int g7 = wid & 7;
    const float gA = gam[g8], gB2 = gam[g8 + 8];
    const float bA = bet[g8], bB2 = bet[g8 + 8];

    float acc[8][4];
#pragma unroll
    for (int nt = 0; nt < 8; nt++)
#pragma unroll
        for (int q = 0; q < 4; q++) acc[nt][q] = 0.f;

    const size_t erow = ((size_t)(b * HN) * NSEQ + (i0 + wid)) * NSEQ + 2 * lane;
    const size_t PL = (size_t)NSEQ * NSEQ;
    const __half* vbase = g_vth + ((size_t)b * DMODEL + wid * HD) * NSEQ;

    uint32_t eraw[16];
#pragma unroll
    for (int h = 0; h < 16; h++)
        eraw[h] = *(const uint32_t*)&g_E[erow + (size_t)h * PL];

    for (int ch = 0; ch < NSEQ / JCH; ch++) {
        const int j0 = ch * JCH;
        // ---- stage E tile [h][j] (warp-private) + v tile -------------------
#pragma unroll
        for (int h = 0; h < 16; h++)
            *(uint32_t*)&et[wid * 1152 + h * FSTR + 2 * lane] = eraw[h];
#pragma unroll
        for (int r = 0; r < 16; r++) {
            int lin = r * 32 + lane;
            int d  = lin >> 3;
            int jq = (lin & 7) * 8;
            float4 v4 = *(const float4*)&vbase[(size_t)d * NSEQ + j0 + jq];
            *(float4*)&vsm[(wid * 64 + d) * FSTR + jq] = v4;
        }
        __syncwarp();
        // ---- talk-mix on tensor cores: t = (W'hi+W'lo) @ E -----------------
        float tacc[8][4];
#pragma unroll
        for (int nt = 0; nt < 8; nt++)
#pragma unroll
            for (int q = 0; q < 4; q++) tacc[nt][q] = 0.f;
#pragma unroll
        for (int np = 0; np < 4; np++) {
            uint32_t bb[4];
            ldsm_x4_t(bb, eB + np * 32);
            mma16816(tacc[2*np],   wh, bb[0], bb[1]);
            mma16816(tacc[2*np],   wl, bb[0], bb[1]);
            mma16816(tacc[2*np+1], wh, bb[2], bb[3]);
            mma16816(tacc[2*np+1], wl, bb[2], bb[3]);
        }
        // ---- LayerNorm across heads (fragment rows) + swizzled aw store ----
#pragma unroll
        for (int nt = 0; nt < 8; nt++) {
            float c0 = tacc[nt][0], c1 = tacc[nt][1];
            float c2 = tacc[nt][2], c3 = tacc[nt][3];
            float s0 = c0 + c2, s1 = c1 + c3;
            float q0 = fmaf(c0, c0, c2 * c2);
            float q1 = fmaf(c1, c1, c3 * c3);
            s0 += __shfl_xor_sync(0xffffffffu, s0, 4);
            s0 += __shfl_xor_sync(0xffffffffu, s0, 8);
            s0 += __shfl_xor_sync(0xffffffffu, s0, 16);
            s1 += __shfl_xor_sync(0xffffffffu, s1, 4);
            s1 += __shfl_xor_sync(0xffffffffu, s1, 8);
            s1 += __shfl_xor_sync(0xffffffffu, s1, 16);
            q0 += __shfl_xor_sync(0xffffffffu, q0, 4);
            q0 += __shfl_xor_sync(0xffffffffu, q0, 8);
            q0 += __shfl_xor_sync(0xffffffffu, q0, 16);
            q1 += __shfl_xor_sync(0xffffffffu, q1, 4);
            q1 += __shfl_xor_sync(0xffffffffu, q1, 8);
            q1 += __shfl_xor_sync(0xffffffffu, q1, 16);
            float mu0 = s0 * (1.f / 16.f), mu1 = s1 * (1.f / 16.f);
            float v0 = fmaf(-mu0, mu0, q0 * (1.f / 16.f));
            float v1 = fmaf(-mu1, mu1, q1 * (1.f / 16.f));
            float r0 = rsqrtf(v0 + LN_EPS), r1 = rsqrtf(v1 + LN_EPS);
            float a0 = fmaf((c0 - mu0) * r0, gA, bA);
            float a1 = fmaf((c1 - mu1) * r1, gA, bA);
            float a2 = fmaf((c2 - mu0) * r0, gB2, bB2);
            float a3 = fmaf((c3 - mu1) * r1, gB2, bB2);
            __half2 hA = __floats2half2_rn(a0, a1);
            __half2 hB = __floats2half2_rn(a2, a3);
            int jb = (nt ^ g8) * 8 + 2 * t;
            *(uint32_t*)&aw[(g8 * 16 + wid) * FSTR + jb]       = *(uint32_t*)&hA;
            *(uint32_t*)&aw[((g8 + 8) * 16 + wid) * FSTR + jb] = *(uint32_t*)&hB;
        }
        __syncthreads();
        // ---- prefetch next chunk's E (hidden under MMAs) -------------------
        if (ch + 1 < NSEQ / JCH) {
#pragma unroll
            for (int h = 0; h < 16; h++)
                eraw[h] = *(const uint32_t*)&g_E[erow + (size_t)h * PL
                                                 + (j0 + JCH)];
        }
        // ---- PV: aw[head wid] (16x64) @ v[wid]^T (64x64) -------------------
#pragma unroll
        for (int ks = 0; ks < 4; ks++) {
            uint32_t a[4];
            uint32_t aAddr = awS
                + (uint32_t)((wid * 16 + (lane & 15)) * (FSTR * 2))
                + (uint32_t)(((((ks << 1) | (lane >> 4)) ^ g7) << 4));
            ldsm_x4(a, aAddr);
#pragma unroll
            for (int np = 0; np < 4; np++) {
                uint32_t bb[4];
                ldsm_x4(bb, bB + np * 16 * FSTR * 2 + ks * 32);
                mma16816(acc[2*np],   a, bb[0], bb[1]);
                mma16816(acc[2*np+1], a, bb[2], bb[3]);
            }
        }
        __syncthreads();
    }

    const int tq = lane & 3;
#pragma unroll
    for (int nt = 0; nt < 8; nt++) {
        int col = wid * HD + nt * 8 + 2 * tq;
        *(float2*)&out[(size_t)(b * NSEQ + i0 + g8) * DMODEL + col]
            = make_float2(acc[nt][0], acc[nt][1]);
        *(float2*)&out[(size_t)(b * NSEQ + i0 + g8 + 8) * DMODEL + col]
            = make_float2(acc[nt][2], acc[nt][3]);
    }
}

__global__ void zero_rowsum_kernel()
{
    int i = blockIdx.x * 256 + threadIdx.x;
    if (i < NB * HN * NSEQ) g_rowsum[i] = 0.f;
}

// ---------------------------------------------------------------------------
extern "C" void kernel_launch(void* const* d_in, const int* in_sizes, int n_in,
                              void* d_out, int out_size)
{
    const float* x       = (const float*)d_in[0];
    const float* context = (const float*)d_in[1];
    const float* Wq      = (const float*)d_in[2];
    const float* Wkv     = (const float*)d_in[3];
    const float* Wtalk   = (const float*)d_in[4];
    const float* gamma   = (const float*)d_in[5];
    const float* beta    = (const float*)d_in[6];
    float* out = (float*)d_out;

    __half *qh, *kh, *vh;
    cudaGetSymbolAddress((void**)&qh, g_qh);
    cudaGetSymbolAddress((void**)&kh, g_kh);
    cudaGetSymbolAddress((void**)&vh, g_vh);

    const int FUSED_SMEM = 221184 + (256 + 32) * 4;
    cudaFuncSetAttribute(fused_pv_kernel,
                         cudaFuncAttributeMaxDynamicSharedMemorySize, FUSED_SMEM);

    zero_rowsum_kernel<<<(NB * HN * NSEQ + 255) / 256, 256>>>();

    // q = x @ Wq^T (scaled) -> fp16; kv = context @ Wkv^T -> k fp16 | v fp16
    gemm_hmma_kernel<<<dim3(DMODEL / 128, (NB * NSEQ) / 128), 256>>>(
        x, Wq, 0.125f, qh, nullptr);
    gemm_hmma_kernel<<<dim3(2048 / 128, (NB * NSEQ) / 128), 256>>>(
        context, Wkv, 1.0f, kh, vh);

    // v -> vt (fp16)
    transpose_v_kernel<<<dim3(NSEQ / 32, DMODEL / 32, NB), dim3(32, 8)>>>();

    // exp(q k^T) per head + row sums (fp16 operands, copy staging)
    scores_hmma_kernel<<<dim3(NSEQ / 128, NSEQ / 128, NB * HN), 256>>>();

    // fused: tensor-core talk mix + LN + (aw @ v) -> out
    fused_pv_kernel<<<dim3(NSEQ / ITILE, NB), 512, FUSED_SMEM>>>(
        out, Wtalk, gamma, beta);
}

// round 16
// speedup vs baseline: 1.0590x; 1.0590x over previous
#include <cuda_runtime.h>
#include <cuda_fp16.h>
#include <cstdint>
#include <cstddef>

#define HN     16
#define DMODEL 1024
#define NSEQ   2048
#define NB     2
#define HD     64
#define LN_EPS 1e-5f
#define SSTR   40          // smem stride (halfs) for k=32 tiles
#define ESTR   136         // smem stride (halfs) for scores E tile (16B rows)
#define FSTR   72          // smem stride (halfs) for fused kernel tiles
#define ITILE  16
#define JCH    64

typedef unsigned long long u64;

// ---------------- scratch (device globals; no allocation allowed) ----------
__device__ __half g_qh [(size_t)NB * NSEQ * DMODEL];     // q fp16 (pre-scaled)
__device__ __half g_kh [(size_t)NB * NSEQ * 1024];       // k fp16
__device__ __half g_vh [(size_t)NB * NSEQ * 1024];       // v fp16 token-major
__device__ __half g_vth[(size_t)NB * DMODEL * NSEQ];     // v fp16 transposed
__device__ __half g_E [(size_t)NB * HN * NSEQ * NSEQ];   // exp(scores), fp16
__device__ float  g_rowsum[NB * HN * NSEQ];

// ---------------- fast exp on the FMA pipe (avoid MUFU.EX2) ----------------
__device__ __forceinline__ float fast_exp(float x) {
    float t = x * 1.4426950408889634f;
    float r = rintf(t);
    float f = t - r;
    float p =      1.5403530394e-4f;
    p = fmaf(p, f, 1.3333558146e-3f);
    p = fmaf(p, f, 9.6181291076e-3f);
    p = fmaf(p, f, 5.5504108665e-2f);
    p = fmaf(p, f, 2.4022650696e-1f);
    p = fmaf(p, f, 6.9314718056e-1f);
    p = fmaf(p, f, 1.0f);
    return p * __int_as_float(((int)r + 127) << 23);
}

// ------------------------- mma.sync / ldmatrix ------------------------------
__device__ __forceinline__ void mma16816(
    float (&c)[4], const uint32_t (&a)[4], uint32_t b0, uint32_t b1)
{
    asm volatile(
        "mma.sync.aligned.m16n8k16.row.col.f32.f16.f16.f32 "
        "{%0,%1,%2,%3}, {%4,%5,%6,%7}, {%8,%9}, {%0,%1,%2,%3};"
        : "+f"(c[0]), "+f"(c[1]), "+f"(c[2]), "+f"(c[3])
        : "r"(a[0]), "r"(a[1]), "r"(a[2]), "r"(a[3]), "r"(b0), "r"(b1));
}
__device__ __forceinline__ void ldsm_x4(uint32_t (&r)[4], uint32_t addr) {
    asm volatile("ldmatrix.sync.aligned.m8n8.x4.shared.b16 {%0,%1,%2,%3}, [%4];"
        : "=r"(r[0]), "=r"(r[1]), "=r"(r[2]), "=r"(r[3]) : "r"(addr));
}

// Stage 128 x 32 fp32 tile as fp16, stride SSTR (gemm inputs).
__device__ __forceinline__ void stage_f32(
    uint16_t* __restrict__ dst, const float* __restrict__ src,
    size_t stride, int tid)
{
#pragma unroll
    for (int s = 0; s < 4; s++) {
        int idx = s * 256 + tid;
        int row = idx >> 3;
        int cg  = idx & 7;
        float4 v = *(const float4*)(src + (size_t)row * stride + cg * 4);
        __half2 h01 = __floats2half2_rn(v.x, v.y);
        __half2 h23 = __floats2half2_rn(v.z, v.w);
        *(uint2*)(dst + row * SSTR + cg * 4)
            = make_uint2(*(uint32_t*)&h01, *(uint32_t*)&h23);
    }
}
// Pure copy of a 128 x 32 fp16 tile into smem (scores staging; no cvt).
__device__ __forceinline__ void stage_copy(
    uint16_t* __restrict__ dst, const __half* __restrict__ src,
    size_t stride, int tid)
{
#pragma unroll
    for (int s = 0; s < 2; s++) {
        int idx = s * 256 + tid;
        int row = idx >> 2;
        int cq  = idx & 3;
        *(uint4*)(dst + row * SSTR + cq * 8)
            = *(const uint4*)(src + (size_t)row * stride + cq * 8);
    }
}

// ---- q/kv GEMM: C[128x128] = A @ B^T, fp32 in, fp16 out -------------------
__global__ void __launch_bounds__(256, 2) gemm_hmma_kernel(
    const float* __restrict__ A, const float* __restrict__ B,
    float alpha, __half* __restrict__ Ck, __half* __restrict__ Cv)
{
    __shared__ __align__(16) uint16_t sA[128 * SSTR];
    __shared__ __align__(16) uint16_t sB[128 * SSTR];
    const int tid  = threadIdx.x;
    const int wid  = tid >> 5;
    const int lane = tid & 31;
    const int wm = wid & 3, wn = wid >> 2;
    const int g = lane >> 2, t = lane & 3;
    const int m0 = blockIdx.y << 7, n0 = blockIdx.x << 7;
    const float* Ap = A + (size_t)m0 * DMODEL;
    const float* Bp = B + (size_t)n0 * DMODEL;

    const uint32_t aoff = (uint32_t)((lane & 15) * (SSTR * 2) + (lane >> 4) * 16);
    const uint32_t boff = (uint32_t)(((lane & 7) + ((lane >> 4) * 8)) * (SSTR * 2)
                                     + ((lane >> 3) & 1) * 16);
    const uint32_t aB = (uint32_t)__cvta_generic_to_shared(sA)
                        + aoff + (uint32_t)(wm * 32 * SSTR * 2);
    const uint32_t bB = (uint32_t)__cvta_generic_to_shared(sB)
                        + boff + (uint32_t)(wn * 64 * SSTR * 2);

    float acc[2][8][4];
#pragma unroll
    for (int mt = 0; mt < 2; mt++)
#pragma unroll
        for (int nt = 0; nt < 8; nt++)
#pragma unroll
            for (int q = 0; q < 4; q++) acc[mt][nt][q] = 0.f;

    for (int i = 0; i < DMODEL / 32; i++) {
        __syncthreads();
        stage_f32(sA, Ap + (size_t)i * 32, DMODEL, tid);
        stage_f32(sB, Bp + (size_t)i * 32, DMODEL, tid);
        __syncthreads();
#pragma unroll
        for (int ks = 0; ks < 2; ks++) {
            uint32_t ah[2][4];
            ldsm_x4(ah[0], aB + ks * 32);
            ldsm_x4(ah[1], aB + 16 * SSTR * 2 + ks * 32);
#pragma unroll
            for (int np = 0; np < 4; np++) {
                uint32_t bh[4];
                ldsm_x4(bh, bB + np * 16 * SSTR * 2 + ks * 32);
                mma16816(acc[0][2*np],   ah[0], bh[0], bh[1]);
                mma16816(acc[1][2*np],   ah[1], bh[0], bh[1]);
                mma16816(acc[0][2*np+1], ah[0], bh[2], bh[3]);
                mma16816(acc[1][2*np+1], ah[1], bh[2], bh[3]);
            }
        }
    }

    const bool isk = (Cv == nullptr) || (n0 < 1024);
    __half* Co = isk ? Ck : Cv;
    const int colbase = isk ? n0 : (n0 - 1024);
#pragma unroll
    for (int mt = 0; mt < 2; mt++) {
        int r0 = m0 + wm * 32 + mt * 16 + g;
#pragma unroll
        for (int nt = 0; nt < 8; nt++) {
            int col = colbase + wn * 64 + nt * 8 + 2 * t;
            __half2 p01 = __floats2half2_rn(acc[mt][nt][0] * alpha,
                                            acc[mt][nt][1] * alpha);
            __half2 p23 = __floats2half2_rn(acc[mt][nt][2] * alpha,
                                            acc[mt][nt][3] * alpha);
            *(uint32_t*)&Co[(size_t)r0 * 1024 + col]       = *(uint32_t*)&p01;
            *(uint32_t*)&Co[(size_t)(r0 + 8) * 1024 + col] = *(uint32_t*)&p23;
        }
    }
}

// ---- scores: E = exp(q k^T) per head, fp16 in/out + rowsum -----------------
// Epilogue round-trips exp results through smem (sE) so the global E store is
// fully coalesced (row-contiguous 16B chunks) instead of 8-row scattered.
__global__ void __launch_bounds__(256, 2) scores_hmma_kernel()
{
    __shared__ __align__(16) uint16_t sA[128 * SSTR];
    __shared__ __align__(16) uint16_t sB[128 * SSTR];
    __shared__ __align__(16) uint16_t sE[128 * ESTR];
    const int tid  = threadIdx.x;
    const int wid  = tid >> 5;
    const int lane = tid & 31;
    const int wm = wid & 3, wn = wid >> 2;
    const int g = lane >> 2, t = lane & 3;
    const int bh = blockIdx.z, b = bh >> 4, h = bh & 15;
    const int i0 = blockIdx.y << 7, j0 = blockIdx.x << 7;

    const __half* Ap = g_qh + (size_t)(b * NSEQ + i0) * DMODEL + h * HD;
    const __half* Bp = g_kh + (size_t)(b * NSEQ + j0) * 1024 + h * HD;
    __half* Cb = g_E + (size_t)bh * NSEQ * NSEQ + (size_t)i0 * NSEQ + j0;
    float* rowsum = g_rowsum + bh * NSEQ + i0;

    const uint32_t aoff = (uint32_t)((lane & 15) * (SSTR * 2) + (lane >> 4) * 16);
    const uint32_t boff = (uint32_t)(((lane & 7) + ((lane >> 4) * 8)) * (SSTR * 2)
                                     + ((lane >> 3) & 1) * 16);
    const uint32_t aB = (uint32_t)__cvta_generic_to_shared(sA)
                        + aoff + (uint32_t)(wm * 32 * SSTR * 2);
    const uint32_t bB = (uint32_t)__cvta_generic_to_shared(sB)
                        + boff + (uint32_t)(wn * 64 * SSTR * 2);

    float acc[2][8][4];
#pragma unroll
    for (int mt = 0; mt < 2; mt++)
#pragma unroll
        for (int nt = 0; nt < 8; nt++)
#pragma unroll
            for (int q = 0; q < 4; q++) acc[mt][nt][q] = 0.f;

#pragma unroll
    for (int i = 0; i < HD / 32; i++) {
        __syncthreads();
        stage_copy(sA, Ap + i * 32, DMODEL, tid);
        stage_copy(sB, Bp + i * 32, 1024, tid);
        __syncthreads();
#pragma unroll
        for (int ks = 0; ks < 2; ks++) {
            uint32_t ah[2][4];
            ldsm_x4(ah[0], aB + ks * 32);
            ldsm_x4(ah[1], aB + 16 * SSTR * 2 + ks * 32);
#pragma unroll
            for (int np = 0; np < 4; np++) {
                uint32_t bh4[4];
                ldsm_x4(bh4, bB + np * 16 * SSTR * 2 + ks * 32);
                mma16816(acc[0][2*np],   ah[0], bh4[0], bh4[1]);
                mma16816(acc[1][2*np],   ah[1], bh4[0], bh4[1]);
                mma16816(acc[0][2*np+1], ah[0], bh4[2], bh4[3]);
                mma16816(acc[1][2*np+1], ah[1], bh4[2], bh4[3]);
            }
        }
    }

    // exp + rowsum; fp16 results into sE (conflict-free: banks = 4g+t)
#pragma unroll
    for (int mt = 0; mt < 2; mt++) {
        int r0 = wm * 32 + mt * 16 + g;
        float rs0 = 0.f, rs1 = 0.f;
#pragma unroll
        for (int nt = 0; nt < 8; nt++) {
            int col = wn * 64 + nt * 8 + 2 * t;
            float e0 = fast_exp(acc[mt][nt][0]);
            float e1 = fast_exp(acc[mt][nt][1]);
            float e2 = fast_exp(acc[mt][nt][2]);
            float e3 = fast_exp(acc[mt][nt][3]);
            rs0 += e0 + e1;
            rs1 += e2 + e3;
            __half2 p01 = __floats2half2_rn(e0, e1);
            __half2 p23 = __floats2half2_rn(e2, e3);
            *(uint32_t*)&sE[r0 * ESTR + col]       = *(uint32_t*)&p01;
            *(uint32_t*)&sE[(r0 + 8) * ESTR + col] = *(uint32_t*)&p23;
        }
        rs0 += __shfl_down_sync(0xffffffffu, rs0, 1, 4);
        rs0 += __shfl_down_sync(0xffffffffu, rs0, 2, 4);
        rs1 += __shfl_down_sync(0xffffffffu, rs1, 1, 4);
        rs1 += __shfl_down_sync(0xffffffffu, rs1, 2, 4);
        if (t == 0) {
            atomicAdd(&rowsum[r0], rs0);
            atomicAdd(&rowsum[r0 + 8], rs1);
        }
    }
    __syncthreads();
    // coalesced E store: thread moves contiguous 16B chunks of whole rows
#pragma unroll
    for (int s = 0; s < 8; s++) {
        int idx = s * 256 + tid;          // 2048 chunks of 16B
        int row = idx >> 4;
        int c16 = idx & 15;
        uint4 v = *(const uint4*)&sE[row * ESTR + c16 * 8];
        *(uint4*)&Cb[(size_t)row * NSEQ + c16 * 8] = v;
    }
}

// --------- transpose v: [b][j][c] fp16 -> [b][c][j] fp16 --------------------
__global__ void __launch_bounds__(256) transpose_v_kernel()
{
    __shared__ __half t[32][33];
    int j0 = blockIdx.x << 5, c0 = blockIdx.y << 5, b = blockIdx.z;
    int tx = threadIdx.x, ty = threadIdx.y;
#pragma unroll
    for (int i = 0; i < 4; i++)
        t[ty + i * 8][tx] =
            g_vh[((size_t)(b * NSEQ) + j0 + ty + i * 8) * 1024 + c0 + tx];
    __syncthreads();
#pragma unroll
    for (int i = 0; i < 4; i++)
        g_vth[((size_t)b * DMODEL + c0 + ty + i * 8) * NSEQ + j0 + tx] =
            t[tx][ty + i * 8];
}

// ---- FUSED: softmax-normalize + talking heads + LN + (aw @ v) --------------
__global__ void __launch_bounds__(512, 1) fused_pv_kernel(
    float* __restrict__ out, const float* __restrict__ Wtalk,
    const float* __restrict__ gamma, const float* __restrict__ beta)
{
    extern __shared__ __align__(16) char sm[];
    __half* aw  = (__half*)sm;                         // 36864 B
    __half* vsm = (__half*)(sm + 36864);               // 147456 B
    float* wst  = (float*)(sm + 36864 + 147456);       // [h][g] 256 floats
    float* rinv = wst + 256;                           // [h][i] 256 floats
    float* gam  = rinv + 256;
    float* bet  = gam + 16;

    const int tid  = threadIdx.x;
    const int wid  = tid >> 5;
    const int lane = tid & 31;
    const int b  = blockIdx.y;
    const int i0 = blockIdx.x * ITILE;

    if (tid < 256) {
        int h = tid >> 4, g = tid & 15;
        wst[tid] = Wtalk[g * 16 + h];                  // wst[h*16+g]
        rinv[tid] = 1.0f / g_rowsum[(size_t)(b * HN + h) * NSEQ + i0 + g];
    }
    if (tid < 16) { gam[tid] = gamma[tid]; bet[tid] = beta[tid]; }
    __syncthreads();

    const uint32_t awS  = (uint32_t)__cvta_generic_to_shared(aw);
    const uint32_t vsmS = (uint32_t)__cvta_generic_to_shared(vsm);
    const uint32_t aB = awS + (uint32_t)(wid * ITILE * FSTR * 2)
                      + (uint32_t)((lane & 15) * (FSTR * 2) + (lane >> 4) * 16);
    const uint32_t bB = vsmS + (uint32_t)(wid * 64 * FSTR * 2)
                      + (uint32_t)(((lane & 7) + ((lane >> 4) * 8)) * (FSTR * 2)
                                   + ((lane >> 3) & 1) * 16);

    float acc[8][4];
#pragma unroll
    for (int nt = 0; nt < 8; nt++)
#pragma unroll
        for (int q = 0; q < 4; q++) acc[nt][q] = 0.f;

    const int i = wid;
    const size_t erow = ((size_t)(b * HN) * NSEQ + (i0 + i)) * NSEQ + 2 * lane;
    const size_t PL = (size_t)NSEQ * NSEQ;
    const __half* vbase = g_vth + ((size_t)b * DMODEL + wid * HD) * NSEQ;

    uint32_t eraw[16];
#pragma unroll
    for (int h = 0; h < 16; h++)
        eraw[h] = *(const uint32_t*)&g_E[erow + (size_t)h * PL];

    for (int ch = 0; ch < NSEQ / JCH; ch++) {
        const int j0 = ch * JCH;
        // ---- phase A: talk + LN for (i, j0+2*lane, j0+2*lane+1) -----------
        float t0[16], t1[16];
#pragma unroll
        for (int g = 0; g < 16; g++) { t0[g] = 0.f; t1[g] = 0.f; }
#pragma unroll
        for (int h = 0; h < 16; h++) {
            float2 ef = __half22float2(*(__half2*)&eraw[h]);
            float r = rinv[h * 16 + i];
            float p0 = ef.x * r, p1 = ef.y * r;
#pragma unroll
            for (int gq = 0; gq < 4; gq++) {
                float4 w4 = *(const float4*)&wst[h * 16 + gq * 4];
                t0[gq*4+0] = fmaf(w4.x, p0, t0[gq*4+0]);
                t1[gq*4+0] = fmaf(w4.x, p1, t1[gq*4+0]);
                t0[gq*4+1] = fmaf(w4.y, p0, t0[gq*4+1]);
                t1[gq*4+1] = fmaf(w4.y, p1, t1[gq*4+1]);
                t0[gq*4+2] = fmaf(w4.z, p0, t0[gq*4+2]);
                t1[gq*4+2] = fmaf(w4.z, p1, t1[gq*4+2]);
                t0[gq*4+3] = fmaf(w4.w, p0, t0[gq*4+3]);
                t1[gq*4+3] = fmaf(w4.w, p1, t1[gq*4+3]);
            }
        }
        float mu0 = 0.f, mu1 = 0.f;
#pragma unroll
        for (int g = 0; g < 16; g++) { mu0 += t0[g]; mu1 += t1[g]; }
        mu0 *= (1.f / 16.f); mu1 *= (1.f / 16.f);
        float v0 = 0.f, v1 = 0.f;
#pragma unroll
        for (int g = 0; g < 16; g++) {
            float d0 = t0[g] - mu0, d1 = t1[g] - mu1;
            v0 = fmaf(d0, d0, v0); v1 = fmaf(d1, d1, v1);
        }
        float rs0 = rsqrtf(v0 * (1.f / 16.f) + LN_EPS);
        float rs1 = rsqrtf(v1 * (1.f / 16.f) + LN_EPS);
#pragma unroll
        for (int g = 0; g < 16; g++) {
            float gg = gam[g], bb = bet[g];
            float a0 = fmaf((t0[g] - mu0) * rs0, gg, bb);
            float a1 = fmaf((t1[g] - mu1) * rs1, gg, bb);
            __half2 hh = __floats2half2_rn(a0, a1);
            *(uint32_t*)&aw[(g * ITILE + i) * FSTR + 2 * lane] = *(uint32_t*)&hh;
        }
        // ---- phase B: warp wid loads its v tile [64 d][64 j] ---------------
#pragma unroll
        for (int r = 0; r < 16; r++) {
            int lin = r * 32 + lane;
            int d  = lin >> 3;
            int jq = (lin & 7) * 8;
            float4 v4 = *(const float4*)&vbase[(size_t)d * NSEQ + j0 + jq];
            *(float4*)&vsm[(wid * 64 + d) * FSTR + jq] = v4;
        }
        __syncthreads();
        // ---- prefetch next chunk's E (hidden under MMAs) -------------------
        if (ch + 1 < NSEQ / JCH) {
#pragma unroll
            for (int h = 0; h < 16; h++)
                eraw[h] = *(const uint32_t*)&g_E[erow + (size_t)h * PL
                                                 + (j0 + JCH)];
        }
        // ---- phase C: MMA  aw[wid] (16x64) @ v[wid]^T (64x64) --------------
#pragma unroll
        for (int ks = 0; ks < 4; ks++) {
            uint32_t a[4];
            ldsm_x4(a, aB + ks * 32);
#pragma unroll
            for (int np = 0; np < 4; np++) {
                uint32_t bb[4];
                ldsm_x4(bb, bB + np * 16 * FSTR * 2 + ks * 32);
                mma16816(acc[2*np],   a, bb[0], bb[1]);
                mma16816(acc[2*np+1], a, bb[2], bb[3]);
            }
        }
        __syncthreads();
    }

    const int g8 = lane >> 2, tq = lane & 3;
#pragma unroll
    for (int nt = 0; nt < 8; nt++) {
        int col = wid * HD + nt * 8 + 2 * tq;
        *(float2*)&out[(size_t)(b * NSEQ + i0 + g8) * DMODEL + col]
            = make_float2(acc[nt][0], acc[nt][1]);
        *(float2*)&out[(size_t)(b * NSEQ + i0 + g8 + 8) * DMODEL + col]
            = make_float2(acc[nt][2], acc[nt][3]);
    }
}

__global__ void zero_rowsum_kernel()
{
    int i = blockIdx.x * 256 + threadIdx.x;
    if (i < NB * HN * NSEQ) g_rowsum[i] = 0.f;
}

// ---------------------------------------------------------------------------
extern "C" void kernel_launch(void* const* d_in, const int* in_sizes, int n_in,
                              void* d_out, int out_size)
{
    const float* x       = (const float*)d_in[0];
    const float* context = (const float*)d_in[1];
    const float* Wq      = (const float*)d_in[2];
    const float* Wkv     = (const float*)d_in[3];
    const float* Wtalk   = (const float*)d_in[4];
    const float* gamma   = (const float*)d_in[5];
    const float* beta    = (const float*)d_in[6];
    float* out = (float*)d_out;

    __half *qh, *kh, *vh;
    cudaGetSymbolAddress((void**)&qh, g_qh);
    cudaGetSymbolAddress((void**)&kh, g_kh);
    cudaGetSymbolAddress((void**)&vh, g_vh);

    const int FUSED_SMEM = 36864 + 147456 + (256 + 256 + 32) * 4;
    cudaFuncSetAttribute(fused_pv_kernel,
                         cudaFuncAttributeMaxDynamicSharedMemorySize, FUSED_SMEM);

    zero_rowsum_kernel<<<(NB * HN * NSEQ + 255) / 256, 256>>>();

    // q = x @ Wq^T (scaled) -> fp16; kv = context @ Wkv^T -> k fp16 | v fp16
    gemm_hmma_kernel<<<dim3(DMODEL / 128, (NB * NSEQ) / 128), 256>>>(
        x, Wq, 0.125f, qh, nullptr);
    gemm_hmma_kernel<<<dim3(2048 / 128, (NB * NSEQ) / 128), 256>>>(
        context, Wkv, 1.0f, kh, vh);

    // v -> vt (fp16)
    transpose_v_kernel<<<dim3(NSEQ / 32, DMODEL / 32, NB), dim3(32, 8)>>>();

    // exp(q k^T) per head + row sums (fp16 operands, coalesced E store)
    scores_hmma_kernel<<<dim3(NSEQ / 128, NSEQ / 128, NB * HN), 256>>>();

    // fused: normalize + talking heads + LN + (aw @ v) -> out
    fused_pv_kernel<<<dim3(NSEQ / ITILE, NB), 512, FUSED_SMEM>>>(
        out, Wtalk, gamma, beta);
}